// round 11
// baseline (speedup 1.0000x reference)
#include <cuda_runtime.h>
#include <cuda_fp16.h>
#include <cstdint>

#define NNODES 50000
#define DDIM 128
#define NH 8
#define HDIM 16
#define FDIM 512
#define E0 800000
#define ETOT 850000
#define EPS_BN 1e-5f
#define NCHUNK 49   // ceil(50000/1024)

// ---------------- scratch (device globals; no allocation allowed) ----------
__device__ __align__(16) __half g_qh[NNODES * DDIM];
__device__ __align__(16) __half g_kh[NNODES * DDIM];
__device__ __align__(16) __half g_vh[NNODES * DDIM];
__device__ __align__(16) __half g_aggt[NNODES * DDIM];
__device__ __align__(16) float  g_x1[NNODES * DDIM];
__device__ __align__(16) __half g_x1t[NNODES * DDIM];
__device__ __align__(16) float  g_tmp[NNODES * DDIM];
__device__ __align__(16) __half g_ff1t[(size_t)NNODES * FDIM];
__device__ __align__(16) __half g_srct[NNODES * DDIM];
__device__ __align__(16) __half g_wt[196608];
__device__ __align__(16) float  g_stats[512];
__device__ int g_src[ETOT];
__device__ int g_dst[ETOT];
__device__ int g_csr[ETOT];
__device__ int g_deg[NNODES];
__device__ int g_rowptr[NNODES + 1];
__device__ int g_cursor[NNODES];
__device__ int g_csum[64];
__device__ int g_is64;

#define WQ_OFF 0
#define WK_OFF 16384
#define WV_OFF 32768
#define WO_OFF 49152
#define W1_OFF 65536
#define W2_OFF 131072
#define NSRC (NNODES * DDIM)
#define NCONV (NSRC + 196608)

// ---------------- prep: dtype detect + zero deg/stats -----------------------
__global__ void prep_kernel(const unsigned int* __restrict__ w) {
    int i = blockIdx.x * blockDim.x + threadIdx.x;
    if (i == 0) {
        int nz = 0;
        for (int j = 1; j < 256; j += 2) nz += (w[j] != 0u);
        g_is64 = (nz == 0) ? 1 : 0;
    }
    if (i < NNODES) g_deg[i] = 0;
    if (i < 512) g_stats[i] = 0.f;
}

// ---------------- decode edges + degree histogram ---------------------------
__global__ void decode_kernel(const unsigned int* __restrict__ w) {
    int e = blockIdx.x * blockDim.x + threadIdx.x;
    if (e >= ETOT) return;
    int s, d;
    if (e < E0) {
        if (g_is64) {
            s = (int)w[2 * (size_t)e];
            d = (int)w[2 * ((size_t)E0 + e)];
        } else {
            s = (int)w[e];
            d = (int)w[E0 + e];
        }
    } else {
        s = d = e - E0;
    }
    g_src[e] = s;
    g_dst[e] = d;
    atomicAdd(&g_deg[d], 1);
}

// ---------------- fp16 conversion: src + all weights ------------------------
__global__ void convert_kernel(const float* __restrict__ src,
                               const float* __restrict__ wq,
                               const float* __restrict__ wk,
                               const float* __restrict__ wv,
                               const float* __restrict__ wo,
                               const float* __restrict__ w1,
                               const float* __restrict__ w2) {
    int i = blockIdx.x * blockDim.x + threadIdx.x;
    int stride = gridDim.x * blockDim.x;
    for (int t = i; t < NCONV; t += stride) {
        if (t < NSRC) {
            g_srct[t] = __float2half_rn(src[t]);
        } else {
            int j = t - NSRC;
            float v;
            if (j < WK_OFF)      v = wq[j - WQ_OFF];
            else if (j < WV_OFF) v = wk[j - WK_OFF];
            else if (j < WO_OFF) v = wv[j - WV_OFF];
            else if (j < W1_OFF) v = wo[j - WO_OFF];
            else if (j < W2_OFF) v = w1[j - W1_OFF];
            else                 v = w2[j - W2_OFF];
            g_wt[j] = __float2half_rn(v);
        }
    }
}

// ---------------- CSR build --------------------------------------------------
__global__ void scan1_kernel() {
    __shared__ int sh[1024];
    int t = threadIdx.x;
    int i = blockIdx.x * 1024 + t;
    int v = (i < NNODES) ? g_deg[i] : 0;
    sh[t] = v;
    __syncthreads();
    for (int off = 1; off < 1024; off <<= 1) {
        int x = (t >= off) ? sh[t - off] : 0;
        __syncthreads();
        sh[t] += x;
        __syncthreads();
    }
    if (i < NNODES) g_rowptr[i] = sh[t] - v;
    if (t == 1023) g_csum[blockIdx.x] = sh[1023];
}

__global__ void scan2_kernel() {
    __shared__ int sh[64];
    int t = threadIdx.x;
    int v = (t < NCHUNK) ? g_csum[t] : 0;
    sh[t] = v;
    __syncthreads();
    for (int off = 1; off < 64; off <<= 1) {
        int x = (t >= off) ? sh[t - off] : 0;
        __syncthreads();
        sh[t] += x;
        __syncthreads();
    }
    if (t < NCHUNK) g_csum[t] = sh[t] - v;  // exclusive
}

__global__ void scan3_kernel() {
    int i = blockIdx.x * blockDim.x + threadIdx.x;
    if (i < NNODES) {
        int rp = g_rowptr[i] + g_csum[i >> 10];
        g_rowptr[i] = rp;
        g_cursor[i] = rp;
    }
    if (i == 0) g_rowptr[NNODES] = ETOT;
}

__global__ void scatter_kernel() {
    int e = blockIdx.x * blockDim.x + threadIdx.x;
    if (e >= ETOT) return;
    int pos = atomicAdd(&g_cursor[g_dst[e]], 1);
    g_csr[pos] = g_src[e];
}

// ---------------- FP16 tensor-core GEMM (m16n8k16) ---------------------------
// Block tile 64(M) x 128(N), k-tile 32 halves, warp tile 32x32 (2x4 warps),
// 256 threads, 3 blocks/SM target for occupancy.
#define GMM 64
#define GNN 128
#define KT 32   // k elements per tile
#define SK 20   // smem word stride (half2 words); conflict-free pattern

__device__ __forceinline__ void mma16(float c[4],
                                      unsigned a0, unsigned a1, unsigned a2, unsigned a3,
                                      unsigned b0, unsigned b1) {
    asm volatile(
        "mma.sync.aligned.m16n8k16.row.col.f32.f16.f16.f32 "
        "{%0,%1,%2,%3}, {%4,%5,%6,%7}, {%8,%9}, {%0,%1,%2,%3};"
        : "+f"(c[0]), "+f"(c[1]), "+f"(c[2]), "+f"(c[3])
        : "r"(a0), "r"(a1), "r"(a2), "r"(a3), "r"(b0), "r"(b1));
}

__device__ __forceinline__ float2 lrelu2(float2 o, int act) {
    if (act) {
        o.x = o.x > 0.f ? o.x : 0.01f * o.x;
        o.y = o.y > 0.f ? o.y : 0.01f * o.y;
    }
    return o;
}

__device__ __forceinline__ void gemm_body(
    const __half* __restrict__ A, const __half* __restrict__ B,
    const float* __restrict__ bias, const float* __restrict__ res,
    float* __restrict__ C, __half* __restrict__ Ct,
    int M, int Nn, int K, float alpha, int act, int stats_off,
    int bm, int bn)
{
    __shared__ __align__(16) unsigned As[2][GMM][SK];
    __shared__ __align__(16) unsigned Bs[2][GNN][SK];
    int tid = threadIdx.x;
    int warp = tid >> 5, lane = tid & 31;
    int wm = warp >> 2, wn = warp & 3;    // 2(M) x 4(N) warps of 32x32
    int gid = lane >> 2, ctg = lane & 3;

    int kw = K >> 1;  // words per row
    // A loader: 1 uint4/thread. row = tid&63, seg = tid>>6 (0..3)
    int arow = tid & 63;
    int aseg = tid >> 6;
    const unsigned* Ap = (const unsigned*)A + (size_t)(bm + arow) * kw + aseg * 4;
    bool aok = (bm + arow) < M;
    // B loader: 2 uint4/thread. row = tid&127, segs (tid>>7)*2, +1
    int brow = tid & 127;
    int bseg = (tid >> 7) * 2;
    const unsigned* Bp = (const unsigned*)B + (size_t)(bn + brow) * kw + bseg * 4;

    float c[2][4][4];
#pragma unroll
    for (int mt = 0; mt < 2; mt++)
#pragma unroll
        for (int nt = 0; nt < 4; nt++)
#pragma unroll
            for (int r = 0; r < 4; r++) c[mt][nt][r] = 0.f;

    const uint4 z4 = make_uint4(0u, 0u, 0u, 0u);
    uint4 av = aok ? *(const uint4*)Ap : z4;
    uint4 b0v = *(const uint4*)Bp;
    uint4 b1v = *(const uint4*)(Bp + 4);
    *(uint4*)&As[0][arow][aseg * 4]       = av;
    *(uint4*)&Bs[0][brow][bseg * 4]       = b0v;
    *(uint4*)&Bs[0][brow][bseg * 4 + 4]   = b1v;
    __syncthreads();

    int nk = K / KT;
    for (int kt = 0; kt < nk; kt++) {
        int cur = kt & 1;
        int nxt = cur ^ 1;
        bool more = (kt + 1) < nk;
        if (more) {
            int off = (kt + 1) * 16;  // words per k-tile
            av  = aok ? *(const uint4*)(Ap + off) : z4;
            b0v = *(const uint4*)(Bp + off);
            b1v = *(const uint4*)(Bp + off + 4);
        }
#pragma unroll
        for (int ks = 0; ks < 2; ks++) {
            int kk = ks * 8;
            unsigned af[2][4], bf[4][2];
#pragma unroll
            for (int mt = 0; mt < 2; mt++) {
                int m = wm * 32 + mt * 16 + gid;
                af[mt][0] = As[cur][m][kk + ctg];
                af[mt][1] = As[cur][m + 8][kk + ctg];
                af[mt][2] = As[cur][m][kk + ctg + 4];
                af[mt][3] = As[cur][m + 8][kk + ctg + 4];
            }
#pragma unroll
            for (int nt = 0; nt < 4; nt++) {
                int n = wn * 32 + nt * 8 + gid;
                bf[nt][0] = Bs[cur][n][kk + ctg];
                bf[nt][1] = Bs[cur][n][kk + ctg + 4];
            }
#pragma unroll
            for (int mt = 0; mt < 2; mt++)
#pragma unroll
                for (int nt = 0; nt < 4; nt++)
                    mma16(c[mt][nt], af[mt][0], af[mt][1], af[mt][2], af[mt][3],
                          bf[nt][0], bf[nt][1]);
        }
        if (more) {
            *(uint4*)&As[nxt][arow][aseg * 4]     = av;
            *(uint4*)&Bs[nxt][brow][bseg * 4]     = b0v;
            *(uint4*)&Bs[nxt][brow][bseg * 4 + 4] = b1v;
            __syncthreads();
        }
    }

    // epilogue
    float ssum[4][2] = {}, ssq[4][2] = {};
#pragma unroll
    for (int nt = 0; nt < 4; nt++) {
        int col = bn + wn * 32 + nt * 8 + 2 * ctg;
        float2 bb = make_float2(0.f, 0.f);
        if (bias) bb = *(const float2*)(bias + col);
#pragma unroll
        for (int mt = 0; mt < 2; mt++) {
            int r0 = bm + wm * 32 + mt * 16 + gid;
            int r1 = r0 + 8;
            if (r0 < M) {
                float2 rv = res ? *(const float2*)(res + (size_t)r0 * Nn + col)
                                : make_float2(0.f, 0.f);
                float2 o;
                o.x = (c[mt][nt][0] + bb.x) * alpha + rv.x;
                o.y = (c[mt][nt][1] + bb.y) * alpha + rv.y;
                o = lrelu2(o, act);
                if (C) *(float2*)(C + (size_t)r0 * Nn + col) = o;
                if (Ct) *(__half2*)(Ct + (size_t)r0 * Nn + col) =
                            __floats2half2_rn(o.x, o.y);
                ssum[nt][0] += o.x; ssum[nt][1] += o.y;
                ssq[nt][0] += o.x * o.x; ssq[nt][1] += o.y * o.y;
            }
            if (r1 < M) {
                float2 rv = res ? *(const float2*)(res + (size_t)r1 * Nn + col)
                                : make_float2(0.f, 0.f);
                float2 o;
                o.x = (c[mt][nt][2] + bb.x) * alpha + rv.x;
                o.y = (c[mt][nt][3] + bb.y) * alpha + rv.y;
                o = lrelu2(o, act);
                if (C) *(float2*)(C + (size_t)r1 * Nn + col) = o;
                if (Ct) *(__half2*)(Ct + (size_t)r1 * Nn + col) =
                            __floats2half2_rn(o.x, o.y);
                ssum[nt][0] += o.x; ssum[nt][1] += o.y;
                ssq[nt][0] += o.x * o.x; ssq[nt][1] += o.y * o.y;
            }
        }
    }

    if (stats_off >= 0) {   // Nn == 128 -> block spans all 128 columns
        __syncthreads();
        float* sh = (float*)&As[0][0][0];  // 256 floats scratch
        sh[tid] = 0.f;
        __syncthreads();
#pragma unroll
        for (int nt = 0; nt < 4; nt++) {
            int cl = wn * 32 + nt * 8 + 2 * ctg;
            atomicAdd(&sh[cl], ssum[nt][0]);
            atomicAdd(&sh[cl + 1], ssum[nt][1]);
            atomicAdd(&sh[128 + cl], ssq[nt][0]);
            atomicAdd(&sh[128 + cl + 1], ssq[nt][1]);
        }
        __syncthreads();
        atomicAdd(&g_stats[stats_off + tid], sh[tid]);
    }
}

__global__ __launch_bounds__(256, 3) void gemm_kernel(
    const __half* __restrict__ A, const __half* __restrict__ B,
    const float* __restrict__ bias, const float* __restrict__ res,
    float* __restrict__ C, __half* __restrict__ Ct,
    int M, int Nn, int K, float alpha, int act, int stats_off)
{
    gemm_body(A, B, bias, res, C, Ct, M, Nn, K, alpha, act, stats_off,
              blockIdx.y * GMM, blockIdx.x * GNN);
}

__global__ __launch_bounds__(256, 3) void qkv_gemm_kernel(const float* __restrict__ qb) {
    int z = blockIdx.z;
    const __half* B = g_wt + ((z == 0) ? WQ_OFF : (z == 1) ? WK_OFF : WV_OFF);
    __half* Ct = (z == 0) ? g_qh : (z == 1) ? g_kh : g_vh;
    const float* bias = (z == 0) ? qb : nullptr;
    float alpha = (z == 0) ? 0.25f : 1.0f;
    gemm_body(g_srct, B, bias, nullptr, nullptr, Ct,
              NNODES, DDIM, DDIM, alpha, 0, -1, blockIdx.y * GMM, 0);
}

// ---------------- warp-per-node CSR attention aggregation -------------------
// fp16 gathers, 8-edge unroll (16 loads in flight), deduped exp.
__global__ void node_agg_kernel() {
    int node = (blockIdx.x * blockDim.x + threadIdx.x) >> 5;
    if (node >= NNODES) return;
    int lane = threadIdx.x & 31;
    uint2 qa = *((const uint2*)(g_qh + (size_t)node * DDIM) + lane);
    float2 qf0 = __half22float2(*(__half2*)&qa.x);
    float2 qf1 = __half22float2(*(__half2*)&qa.y);
    float4 acc = make_float4(0.f, 0.f, 0.f, 0.f);
    float den = 0.f;
    int beg = g_rowptr[node], end = g_rowptr[node + 1];
    int i = beg;
    int esel = lane & 3;
    int gbase = lane & ~3;
    for (; i + 8 <= end; i += 8) {
        int sv = (lane < 8) ? g_csr[i + lane] : 0;
        int s[8];
#pragma unroll
        for (int j = 0; j < 8; j++) s[j] = __shfl_sync(0xffffffffu, sv, j);
        uint2 kr[8], vr[8];
#pragma unroll
        for (int j = 0; j < 8; j++)
            kr[j] = *((const uint2*)(g_kh + (size_t)s[j] * DDIM) + lane);
#pragma unroll
        for (int j = 0; j < 8; j++)
            vr[j] = *((const uint2*)(g_vh + (size_t)s[j] * DDIM) + lane);
        float p[8];
#pragma unroll
        for (int j = 0; j < 8; j++) {
            float2 k0 = __half22float2(*(__half2*)&kr[j].x);
            float2 k1 = __half22float2(*(__half2*)&kr[j].y);
            p[j] = k0.x * qf0.x + k0.y * qf0.y + k1.x * qf1.x + k1.y * qf1.y;
            p[j] += __shfl_xor_sync(0xffffffffu, p[j], 1);
            p[j] += __shfl_xor_sync(0xffffffffu, p[j], 2);
        }
        float eoA = __expf(esel == 0 ? p[0] : esel == 1 ? p[1]
                           : esel == 2 ? p[2] : p[3]);
        float eoB = __expf(esel == 0 ? p[4] : esel == 1 ? p[5]
                           : esel == 2 ? p[6] : p[7]);
        float e[8];
#pragma unroll
        for (int j = 0; j < 4; j++) {
            e[j]     = __shfl_sync(0xffffffffu, eoA, gbase + j);
            e[4 + j] = __shfl_sync(0xffffffffu, eoB, gbase + j);
        }
#pragma unroll
        for (int j = 0; j < 8; j++) {
            den += e[j];
            float2 v0 = __half22float2(*(__half2*)&vr[j].x);
            float2 v1 = __half22float2(*(__half2*)&vr[j].y);
            acc.x += e[j] * v0.x; acc.y += e[j] * v0.y;
            acc.z += e[j] * v1.x; acc.w += e[j] * v1.y;
        }
    }
    for (; i < end; i++) {
        int s0 = __shfl_sync(0xffffffffu, (lane == 0) ? g_csr[i] : 0, 0);
        uint2 kr = *((const uint2*)(g_kh + (size_t)s0 * DDIM) + lane);
        float2 k0 = __half22float2(*(__half2*)&kr.x);
        float2 k1 = __half22float2(*(__half2*)&kr.y);
        float p = k0.x * qf0.x + k0.y * qf0.y + k1.x * qf1.x + k1.y * qf1.y;
        p += __shfl_xor_sync(0xffffffffu, p, 1);
        p += __shfl_xor_sync(0xffffffffu, p, 2);
        float e0 = __expf(p);
        den += e0;
        uint2 vr = *((const uint2*)(g_vh + (size_t)s0 * DDIM) + lane);
        float2 v0 = __half22float2(*(__half2*)&vr.x);
        float2 v1 = __half22float2(*(__half2*)&vr.y);
        acc.x += e0 * v0.x; acc.y += e0 * v0.y;
        acc.z += e0 * v1.x; acc.w += e0 * v1.y;
    }
    float inv = 1.f / (den + 1e-16f);
    __half2 o0 = __floats2half2_rn(acc.x * inv, acc.y * inv);
    __half2 o1 = __floats2half2_rn(acc.z * inv, acc.w * inv);
    uint2 o;
    o.x = *(unsigned*)&o0;
    o.y = *(unsigned*)&o1;
    *((uint2*)(g_aggt + (size_t)node * DDIM) + lane) = o;
}

// ---------------- BatchNorm apply -------------------------------------------
__global__ void bn_apply_kernel(const float* __restrict__ X, int off,
                                const float* __restrict__ gamma,
                                const float* __restrict__ beta,
                                float* __restrict__ Y,
                                __half* __restrict__ Yt) {
    int i = blockIdx.x * blockDim.x + threadIdx.x;
    if (i >= NNODES * DDIM) return;
    int j = i & (DDIM - 1);
    const float invn = 1.0f / NNODES;
    float mean = g_stats[off + j] * invn;
    float var = g_stats[off + DDIM + j] * invn - mean * mean;
    float val = (X[i] - mean) * rsqrtf(var + EPS_BN) * gamma[j] + beta[j];
    Y[i] = val;
    if (Yt) Yt[i] = __float2half_rn(val);
}

// ---------------- launch ------------------------------------------------------
extern "C" void kernel_launch(void* const* d_in, const int* in_sizes, int n_in,
                              void* d_out, int out_size) {
    const float* src    = (const float*)d_in[0];
    const unsigned int* ei = (const unsigned int*)d_in[1];
    const float* q_w    = (const float*)d_in[2];
    const float* q_b    = (const float*)d_in[3];
    const float* k_w    = (const float*)d_in[4];
    const float* v_w    = (const float*)d_in[5];
    const float* out_w  = (const float*)d_in[6];
    const float* out_b  = (const float*)d_in[7];
    const float* g1     = (const float*)d_in[8];
    const float* b1     = (const float*)d_in[9];
    const float* lin1_w = (const float*)d_in[10];
    const float* lin1_b = (const float*)d_in[11];
    const float* lin2_w = (const float*)d_in[12];
    const float* lin2_b = (const float*)d_in[13];
    const float* g2     = (const float*)d_in[14];
    const float* b2     = (const float*)d_in[15];
    float* out = (float*)d_out;

    __half *paggt, *px1t, *pff1t, *pwt;
    float *px1, *ptmp;
    cudaGetSymbolAddress((void**)&paggt, g_aggt);
    cudaGetSymbolAddress((void**)&px1,   g_x1);
    cudaGetSymbolAddress((void**)&px1t,  g_x1t);
    cudaGetSymbolAddress((void**)&ptmp,  g_tmp);
    cudaGetSymbolAddress((void**)&pff1t, g_ff1t);
    cudaGetSymbolAddress((void**)&pwt,   g_wt);

    const int MB = (NNODES + GMM - 1) / GMM;  // 782

    convert_kernel<<<512, 256>>>(src, q_w, k_w, v_w, out_w, lin1_w, lin2_w);
    prep_kernel<<<(NNODES + 255) / 256, 256>>>(ei);
    decode_kernel<<<(ETOT + 255) / 256, 256>>>(ei);
    qkv_gemm_kernel<<<dim3(1, MB, 3), 256>>>(q_b);
    scan1_kernel<<<NCHUNK, 1024>>>();
    scan2_kernel<<<1, 64>>>();
    scan3_kernel<<<(NNODES + 255) / 256, 256>>>();
    scatter_kernel<<<(ETOT + 255) / 256, 256>>>();

    // attention aggregation (CSR, warp per node)
    node_agg_kernel<<<(NNODES * 32 + 255) / 256, 256>>>();

    // out projection + residual + fused BN1 stats
    gemm_kernel<<<dim3(1, MB), 256>>>(paggt, pwt + WO_OFF, out_b, src,
                                      ptmp, nullptr, NNODES, DDIM, DDIM,
                                      1.0f, 0, 0);

    // BN1 apply (fp32 + fp16)
    bn_apply_kernel<<<(NNODES * DDIM + 255) / 256, 256>>>(ptmp, 0, g1, b1,
                                                          px1, px1t);

    // FFN
    gemm_kernel<<<dim3(FDIM / GNN, MB), 256>>>(px1t, pwt + W1_OFF, lin1_b,
                                               nullptr, nullptr, pff1t,
                                               NNODES, FDIM, DDIM, 1.0f, 1, -1);
    gemm_kernel<<<dim3(1, MB), 256>>>(pff1t, pwt + W2_OFF, lin2_b, px1,
                                      ptmp, nullptr, NNODES, DDIM, FDIM,
                                      1.0f, 0, 256);

    // BN2 apply -> output
    bn_apply_kernel<<<(NNODES * DDIM + 255) / 256, 256>>>(ptmp, 256, g2, b2,
                                                          out, nullptr);
}

// round 12
// speedup vs baseline: 1.0583x; 1.0583x over previous
#include <cuda_runtime.h>
#include <cuda_fp16.h>
#include <cstdint>

#define NNODES 50000
#define DDIM 128
#define NH 8
#define HDIM 16
#define FDIM 512
#define E0 800000
#define ETOT 850000
#define EPS_BN 1e-5f
#define NCHUNK 49   // ceil(50000/1024)

// ---------------- scratch (device globals; no allocation allowed) ----------
__device__ __align__(16) __half g_qh[NNODES * DDIM];
__device__ __align__(16) __half g_kh[NNODES * DDIM];
__device__ __align__(16) __half g_vh[NNODES * DDIM];
__device__ __align__(16) __half g_aggt[NNODES * DDIM];
__device__ __align__(16) float  g_x1[NNODES * DDIM];
__device__ __align__(16) __half g_x1t[NNODES * DDIM];
__device__ __align__(16) float  g_tmp[NNODES * DDIM];
__device__ __align__(16) __half g_ff1t[(size_t)NNODES * FDIM];
__device__ __align__(16) __half g_srct[NNODES * DDIM];
__device__ __align__(16) __half g_wt[196608];
__device__ __align__(16) float  g_stats[512];
__device__ int g_src[ETOT];
__device__ int g_dst[ETOT];
__device__ int g_csr[ETOT];
__device__ int g_deg[NNODES];
__device__ int g_rowptr[NNODES + 1];
__device__ int g_cursor[NNODES];
__device__ int g_csum[64];
__device__ int g_is64;

#define WQ_OFF 0
#define WK_OFF 16384
#define WV_OFF 32768
#define WO_OFF 49152
#define W1_OFF 65536
#define W2_OFF 131072
#define NSRC (NNODES * DDIM)
#define NCONV (NSRC + 196608)

// ---------------- prep: dtype detect + zero deg/stats -----------------------
__global__ void prep_kernel(const unsigned int* __restrict__ w) {
    int i = blockIdx.x * blockDim.x + threadIdx.x;
    if (i == 0) {
        int nz = 0;
        for (int j = 1; j < 256; j += 2) nz += (w[j] != 0u);
        g_is64 = (nz == 0) ? 1 : 0;
    }
    if (i < NNODES) g_deg[i] = 0;
    if (i < 512) g_stats[i] = 0.f;
}

// ---------------- decode edges + degree histogram ---------------------------
__global__ void decode_kernel(const unsigned int* __restrict__ w) {
    int e = blockIdx.x * blockDim.x + threadIdx.x;
    if (e >= ETOT) return;
    int s, d;
    if (e < E0) {
        if (g_is64) {
            s = (int)w[2 * (size_t)e];
            d = (int)w[2 * ((size_t)E0 + e)];
        } else {
            s = (int)w[e];
            d = (int)w[E0 + e];
        }
    } else {
        s = d = e - E0;
    }
    g_src[e] = s;
    g_dst[e] = d;
    atomicAdd(&g_deg[d], 1);
}

// ---------------- fp16 conversion: src + all weights ------------------------
__global__ void convert_kernel(const float* __restrict__ src,
                               const float* __restrict__ wq,
                               const float* __restrict__ wk,
                               const float* __restrict__ wv,
                               const float* __restrict__ wo,
                               const float* __restrict__ w1,
                               const float* __restrict__ w2) {
    int i = blockIdx.x * blockDim.x + threadIdx.x;
    int stride = gridDim.x * blockDim.x;
    for (int t = i; t < NCONV; t += stride) {
        if (t < NSRC) {
            g_srct[t] = __float2half_rn(src[t]);
        } else {
            int j = t - NSRC;
            float v;
            if (j < WK_OFF)      v = wq[j - WQ_OFF];
            else if (j < WV_OFF) v = wk[j - WK_OFF];
            else if (j < WO_OFF) v = wv[j - WV_OFF];
            else if (j < W1_OFF) v = wo[j - WO_OFF];
            else if (j < W2_OFF) v = w1[j - W1_OFF];
            else                 v = w2[j - W2_OFF];
            g_wt[j] = __float2half_rn(v);
        }
    }
}

// ---------------- CSR build --------------------------------------------------
__global__ void scan1_kernel() {
    __shared__ int sh[1024];
    int t = threadIdx.x;
    int i = blockIdx.x * 1024 + t;
    int v = (i < NNODES) ? g_deg[i] : 0;
    sh[t] = v;
    __syncthreads();
    for (int off = 1; off < 1024; off <<= 1) {
        int x = (t >= off) ? sh[t - off] : 0;
        __syncthreads();
        sh[t] += x;
        __syncthreads();
    }
    if (i < NNODES) g_rowptr[i] = sh[t] - v;
    if (t == 1023) g_csum[blockIdx.x] = sh[1023];
}

__global__ void scan2_kernel() {
    __shared__ int sh[64];
    int t = threadIdx.x;
    int v = (t < NCHUNK) ? g_csum[t] : 0;
    sh[t] = v;
    __syncthreads();
    for (int off = 1; off < 64; off <<= 1) {
        int x = (t >= off) ? sh[t - off] : 0;
        __syncthreads();
        sh[t] += x;
        __syncthreads();
    }
    if (t < NCHUNK) g_csum[t] = sh[t] - v;  // exclusive
}

__global__ void scan3_kernel() {
    int i = blockIdx.x * blockDim.x + threadIdx.x;
    if (i < NNODES) {
        int rp = g_rowptr[i] + g_csum[i >> 10];
        g_rowptr[i] = rp;
        g_cursor[i] = rp;
    }
    if (i == 0) g_rowptr[NNODES] = ETOT;
}

__global__ void scatter_kernel() {
    int e = blockIdx.x * blockDim.x + threadIdx.x;
    if (e >= ETOT) return;
    int pos = atomicAdd(&g_cursor[g_dst[e]], 1);
    g_csr[pos] = g_src[e];
}

// ---------------- FP16 tensor-core GEMM (m16n8k16 + ldmatrix) ---------------
// Block 128x128, k-tile 32 halves, warp tile 64x32 (2x4 warps), 256 threads.
#define GM 128
#define GN 128
#define KT 32   // k elements per tile
#define SK 20   // smem word stride (half2 words); conflict-free for STS + LDSM
#define BUFB (GM * SK * 4)   // bytes per buffer (As and Bs identical)

__device__ __forceinline__ void mma16(float c[4],
                                      unsigned a0, unsigned a1, unsigned a2, unsigned a3,
                                      unsigned b0, unsigned b1) {
    asm volatile(
        "mma.sync.aligned.m16n8k16.row.col.f32.f16.f16.f32 "
        "{%0,%1,%2,%3}, {%4,%5,%6,%7}, {%8,%9}, {%0,%1,%2,%3};"
        : "+f"(c[0]), "+f"(c[1]), "+f"(c[2]), "+f"(c[3])
        : "r"(a0), "r"(a1), "r"(a2), "r"(a3), "r"(b0), "r"(b1));
}

#define LDSM4(r0, r1, r2, r3, addr) \
    asm volatile("ldmatrix.sync.aligned.m8n8.x4.shared.b16 {%0,%1,%2,%3}, [%4];" \
                 : "=r"(r0), "=r"(r1), "=r"(r2), "=r"(r3) : "r"(addr))

__device__ __forceinline__ float2 lrelu2(float2 o, int act) {
    if (act) {
        o.x = o.x > 0.f ? o.x : 0.01f * o.x;
        o.y = o.y > 0.f ? o.y : 0.01f * o.y;
    }
    return o;
}

__device__ __forceinline__ void gemm_body(
    const __half* __restrict__ A, const __half* __restrict__ B,
    const float* __restrict__ bias, const float* __restrict__ res,
    float* __restrict__ C, __half* __restrict__ Ct,
    int M, int Nn, int K, float alpha, int act, int stats_off,
    int bm, int bn)
{
    __shared__ __align__(16) unsigned As[2][GM][SK];
    __shared__ __align__(16) unsigned Bs[2][GN][SK];
    int tid = threadIdx.x;
    int warp = tid >> 5, lane = tid & 31;
    int wm = warp >> 2, wn = warp & 3;    // 2(M) x 4(N) warps
    int gid = lane >> 2, ctg = lane & 3;
    int lg = lane >> 3, l8 = lane & 7;    // ldmatrix lane groups

    int lrow = tid & 127;
    int kh = (tid >> 7) * 8;
    int kw = K >> 1;
    const unsigned* Ap = (const unsigned*)A + (size_t)(bm + lrow) * kw + kh;
    const unsigned* Bp = (const unsigned*)B + (size_t)(bn + lrow) * kw + kh;
    bool aok = (bm + lrow) < M;

    // per-lane ldmatrix base addresses (buffer 0, ks 0)
    unsigned sA = (unsigned)__cvta_generic_to_shared(&As[0][0][0]);
    unsigned sB = (unsigned)__cvta_generic_to_shared(&Bs[0][0][0]);
    unsigned aBase = sA + (unsigned)((wm * 64 + (lg & 1) * 8 + l8) * (SK * 4)
                                     + (lg >> 1) * 16);
    unsigned bBase = sB + (unsigned)((wn * 32 + (lg >> 1) * 8 + l8) * (SK * 4)
                                     + (lg & 1) * 16);

    float c[4][4][4];
#pragma unroll
    for (int mt = 0; mt < 4; mt++)
#pragma unroll
        for (int nt = 0; nt < 4; nt++)
#pragma unroll
            for (int r = 0; r < 4; r++) c[mt][nt][r] = 0.f;

    const uint4 z4 = make_uint4(0u, 0u, 0u, 0u);
    uint4 a0v = aok ? *(const uint4*)Ap : z4;
    uint4 a1v = aok ? *(const uint4*)(Ap + 4) : z4;
    uint4 b0v = *(const uint4*)Bp;
    uint4 b1v = *(const uint4*)(Bp + 4);
    *(uint4*)&As[0][lrow][kh]     = a0v;
    *(uint4*)&As[0][lrow][kh + 4] = a1v;
    *(uint4*)&Bs[0][lrow][kh]     = b0v;
    *(uint4*)&Bs[0][lrow][kh + 4] = b1v;
    __syncthreads();

    int nk = K / KT;
    for (int kt = 0; kt < nk; kt++) {
        int cur = kt & 1;
        int nxt = cur ^ 1;
        bool more = (kt + 1) < nk;
        if (more) {
            int off = (kt + 1) * 16;
            a0v = aok ? *(const uint4*)(Ap + off) : z4;
            a1v = aok ? *(const uint4*)(Ap + off + 4) : z4;
            b0v = *(const uint4*)(Bp + off);
            b1v = *(const uint4*)(Bp + off + 4);
        }
        unsigned aB = aBase + cur * BUFB;
        unsigned bB = bBase + cur * BUFB;
#pragma unroll
        for (int ks = 0; ks < 2; ks++) {
            unsigned ksoff = ks * 32;  // 8 words
            unsigned af[4][4], bf[4][2];
#pragma unroll
            for (int mt = 0; mt < 4; mt++)
                LDSM4(af[mt][0], af[mt][1], af[mt][2], af[mt][3],
                      aB + mt * (16 * SK * 4) + ksoff);
#pragma unroll
            for (int np = 0; np < 2; np++)
                LDSM4(bf[np * 2][0], bf[np * 2][1], bf[np * 2 + 1][0],
                      bf[np * 2 + 1][1], bB + np * (16 * SK * 4) + ksoff);
#pragma unroll
            for (int mt = 0; mt < 4; mt++)
#pragma unroll
                for (int nt = 0; nt < 4; nt++)
                    mma16(c[mt][nt], af[mt][0], af[mt][1], af[mt][2], af[mt][3],
                          bf[nt][0], bf[nt][1]);
        }
        if (more) {
            *(uint4*)&As[nxt][lrow][kh]     = a0v;
            *(uint4*)&As[nxt][lrow][kh + 4] = a1v;
            *(uint4*)&Bs[nxt][lrow][kh]     = b0v;
            *(uint4*)&Bs[nxt][lrow][kh + 4] = b1v;
            __syncthreads();
        }
    }

    // epilogue
    float ssum[4][2] = {}, ssq[4][2] = {};
#pragma unroll
    for (int nt = 0; nt < 4; nt++) {
        int col = bn + wn * 32 + nt * 8 + 2 * ctg;
        float2 bb = make_float2(0.f, 0.f);
        if (bias) bb = *(const float2*)(bias + col);
#pragma unroll
        for (int mt = 0; mt < 4; mt++) {
            int r0 = bm + wm * 64 + mt * 16 + gid;
            int r1 = r0 + 8;
            if (r0 < M) {
                float2 rv = res ? *(const float2*)(res + (size_t)r0 * Nn + col)
                                : make_float2(0.f, 0.f);
                float2 o;
                o.x = (c[mt][nt][0] + bb.x) * alpha + rv.x;
                o.y = (c[mt][nt][1] + bb.y) * alpha + rv.y;
                o = lrelu2(o, act);
                if (C) *(float2*)(C + (size_t)r0 * Nn + col) = o;
                if (Ct) *(__half2*)(Ct + (size_t)r0 * Nn + col) =
                            __floats2half2_rn(o.x, o.y);
                ssum[nt][0] += o.x; ssum[nt][1] += o.y;
                ssq[nt][0] += o.x * o.x; ssq[nt][1] += o.y * o.y;
            }
            if (r1 < M) {
                float2 rv = res ? *(const float2*)(res + (size_t)r1 * Nn + col)
                                : make_float2(0.f, 0.f);
                float2 o;
                o.x = (c[mt][nt][2] + bb.x) * alpha + rv.x;
                o.y = (c[mt][nt][3] + bb.y) * alpha + rv.y;
                o = lrelu2(o, act);
                if (C) *(float2*)(C + (size_t)r1 * Nn + col) = o;
                if (Ct) *(__half2*)(Ct + (size_t)r1 * Nn + col) =
                            __floats2half2_rn(o.x, o.y);
                ssum[nt][0] += o.x; ssum[nt][1] += o.y;
                ssq[nt][0] += o.x * o.x; ssq[nt][1] += o.y * o.y;
            }
        }
    }

    if (stats_off >= 0) {
        __syncthreads();
        float* sh = (float*)&As[0][0][0];
        sh[tid] = 0.f;
        __syncthreads();
#pragma unroll
        for (int nt = 0; nt < 4; nt++) {
            int cl = wn * 32 + nt * 8 + 2 * ctg;
            atomicAdd(&sh[cl], ssum[nt][0]);
            atomicAdd(&sh[cl + 1], ssum[nt][1]);
            atomicAdd(&sh[128 + cl], ssq[nt][0]);
            atomicAdd(&sh[128 + cl + 1], ssq[nt][1]);
        }
        __syncthreads();
        atomicAdd(&g_stats[stats_off + tid], sh[tid]);
    }
}

__global__ __launch_bounds__(256, 2) void gemm_kernel(
    const __half* __restrict__ A, const __half* __restrict__ B,
    const float* __restrict__ bias, const float* __restrict__ res,
    float* __restrict__ C, __half* __restrict__ Ct,
    int M, int Nn, int K, float alpha, int act, int stats_off)
{
    gemm_body(A, B, bias, res, C, Ct, M, Nn, K, alpha, act, stats_off,
              blockIdx.y * GM, blockIdx.x * GN);
}

__global__ __launch_bounds__(256, 2) void qkv_gemm_kernel(const float* __restrict__ qb) {
    int z = blockIdx.z;
    const __half* B = g_wt + ((z == 0) ? WQ_OFF : (z == 1) ? WK_OFF : WV_OFF);
    __half* Ct = (z == 0) ? g_qh : (z == 1) ? g_kh : g_vh;
    const float* bias = (z == 0) ? qb : nullptr;
    float alpha = (z == 0) ? 0.25f : 1.0f;
    gemm_body(g_srct, B, bias, nullptr, nullptr, Ct,
              NNODES, DDIM, DDIM, alpha, 0, -1, blockIdx.y * GM, 0);
}

// ---------------- warp-per-node CSR attention aggregation -------------------
// fp16 gathers, 4-edge unroll, deduped exp (R10 known-good version).
__global__ void node_agg_kernel() {
    int node = (blockIdx.x * blockDim.x + threadIdx.x) >> 5;
    if (node >= NNODES) return;
    int lane = threadIdx.x & 31;
    uint2 qa = *((const uint2*)(g_qh + (size_t)node * DDIM) + lane);
    float2 qf0 = __half22float2(*(__half2*)&qa.x);
    float2 qf1 = __half22float2(*(__half2*)&qa.y);
    float4 acc = make_float4(0.f, 0.f, 0.f, 0.f);
    float den = 0.f;
    int beg = g_rowptr[node], end = g_rowptr[node + 1];
    int i = beg;
    int esel = lane & 3;
    int gbase = lane & ~3;
    for (; i + 4 <= end; i += 4) {
        int sv = (lane < 4) ? g_csr[i + lane] : 0;
        int s[4];
#pragma unroll
        for (int j = 0; j < 4; j++) s[j] = __shfl_sync(0xffffffffu, sv, j);
        uint2 kr[4];
#pragma unroll
        for (int j = 0; j < 4; j++)
            kr[j] = *((const uint2*)(g_kh + (size_t)s[j] * DDIM) + lane);
        float p[4];
#pragma unroll
        for (int j = 0; j < 4; j++) {
            float2 k0 = __half22float2(*(__half2*)&kr[j].x);
            float2 k1 = __half22float2(*(__half2*)&kr[j].y);
            p[j] = k0.x * qf0.x + k0.y * qf0.y + k1.x * qf1.x + k1.y * qf1.y;
            p[j] += __shfl_xor_sync(0xffffffffu, p[j], 1);
            p[j] += __shfl_xor_sync(0xffffffffu, p[j], 2);
        }
        float eo = __expf(esel == 0 ? p[0] : esel == 1 ? p[1]
                          : esel == 2 ? p[2] : p[3]);
        float e[4];
#pragma unroll
        for (int j = 0; j < 4; j++)
            e[j] = __shfl_sync(0xffffffffu, eo, gbase + j);
        uint2 vr[4];
#pragma unroll
        for (int j = 0; j < 4; j++)
            vr[j] = *((const uint2*)(g_vh + (size_t)s[j] * DDIM) + lane);
#pragma unroll
        for (int j = 0; j < 4; j++) {
            den += e[j];
            float2 v0 = __half22float2(*(__half2*)&vr[j].x);
            float2 v1 = __half22float2(*(__half2*)&vr[j].y);
            acc.x += e[j] * v0.x; acc.y += e[j] * v0.y;
            acc.z += e[j] * v1.x; acc.w += e[j] * v1.y;
        }
    }
    for (; i < end; i++) {
        int s0 = __shfl_sync(0xffffffffu, (lane == 0) ? g_csr[i] : 0, 0);
        uint2 kr = *((const uint2*)(g_kh + (size_t)s0 * DDIM) + lane);
        float2 k0 = __half22float2(*(__half2*)&kr.x);
        float2 k1 = __half22float2(*(__half2*)&kr.y);
        float p = k0.x * qf0.x + k0.y * qf0.y + k1.x * qf1.x + k1.y * qf1.y;
        p += __shfl_xor_sync(0xffffffffu, p, 1);
        p += __shfl_xor_sync(0xffffffffu, p, 2);
        float e0 = __expf(p);
        den += e0;
        uint2 vr = *((const uint2*)(g_vh + (size_t)s0 * DDIM) + lane);
        float2 v0 = __half22float2(*(__half2*)&vr.x);
        float2 v1 = __half22float2(*(__half2*)&vr.y);
        acc.x += e0 * v0.x; acc.y += e0 * v0.y;
        acc.z += e0 * v1.x; acc.w += e0 * v1.y;
    }
    float inv = 1.f / (den + 1e-16f);
    __half2 o0 = __floats2half2_rn(acc.x * inv, acc.y * inv);
    __half2 o1 = __floats2half2_rn(acc.z * inv, acc.w * inv);
    uint2 o;
    o.x = *(unsigned*)&o0;
    o.y = *(unsigned*)&o1;
    *((uint2*)(g_aggt + (size_t)node * DDIM) + lane) = o;
}

// ---------------- BatchNorm apply -------------------------------------------
__global__ void bn_apply_kernel(const float* __restrict__ X, int off,
                                const float* __restrict__ gamma,
                                const float* __restrict__ beta,
                                float* __restrict__ Y,
                                __half* __restrict__ Yt) {
    int i = blockIdx.x * blockDim.x + threadIdx.x;
    if (i >= NNODES * DDIM) return;
    int j = i & (DDIM - 1);
    const float invn = 1.0f / NNODES;
    float mean = g_stats[off + j] * invn;
    float var = g_stats[off + DDIM + j] * invn - mean * mean;
    float val = (X[i] - mean) * rsqrtf(var + EPS_BN) * gamma[j] + beta[j];
    Y[i] = val;
    if (Yt) Yt[i] = __float2half_rn(val);
}

// ---------------- launch ------------------------------------------------------
extern "C" void kernel_launch(void* const* d_in, const int* in_sizes, int n_in,
                              void* d_out, int out_size) {
    const float* src    = (const float*)d_in[0];
    const unsigned int* ei = (const unsigned int*)d_in[1];
    const float* q_w    = (const float*)d_in[2];
    const float* q_b    = (const float*)d_in[3];
    const float* k_w    = (const float*)d_in[4];
    const float* v_w    = (const float*)d_in[5];
    const float* out_w  = (const float*)d_in[6];
    const float* out_b  = (const float*)d_in[7];
    const float* g1     = (const float*)d_in[8];
    const float* b1     = (const float*)d_in[9];
    const float* lin1_w = (const float*)d_in[10];
    const float* lin1_b = (const float*)d_in[11];
    const float* lin2_w = (const float*)d_in[12];
    const float* lin2_b = (const float*)d_in[13];
    const float* g2     = (const float*)d_in[14];
    const float* b2     = (const float*)d_in[15];
    float* out = (float*)d_out;

    __half *paggt, *px1t, *pff1t, *pwt;
    float *px1, *ptmp;
    cudaGetSymbolAddress((void**)&paggt, g_aggt);
    cudaGetSymbolAddress((void**)&px1,   g_x1);
    cudaGetSymbolAddress((void**)&px1t,  g_x1t);
    cudaGetSymbolAddress((void**)&ptmp,  g_tmp);
    cudaGetSymbolAddress((void**)&pff1t, g_ff1t);
    cudaGetSymbolAddress((void**)&pwt,   g_wt);

    const int MB = (NNODES + GM - 1) / GM;  // 391

    convert_kernel<<<512, 256>>>(src, q_w, k_w, v_w, out_w, lin1_w, lin2_w);
    prep_kernel<<<(NNODES + 255) / 256, 256>>>(ei);
    decode_kernel<<<(ETOT + 255) / 256, 256>>>(ei);
    qkv_gemm_kernel<<<dim3(1, MB, 3), 256>>>(q_b);
    scan1_kernel<<<NCHUNK, 1024>>>();
    scan2_kernel<<<1, 64>>>();
    scan3_kernel<<<(NNODES + 255) / 256, 256>>>();
    scatter_kernel<<<(ETOT + 255) / 256, 256>>>();

    // attention aggregation (CSR, warp per node)
    node_agg_kernel<<<(NNODES * 32 + 255) / 256, 256>>>();

    // out projection + residual + fused BN1 stats
    gemm_kernel<<<dim3(1, MB), 256>>>(paggt, pwt + WO_OFF, out_b, src,
                                      ptmp, nullptr, NNODES, DDIM, DDIM,
                                      1.0f, 0, 0);

    // BN1 apply (fp32 + fp16)
    bn_apply_kernel<<<(NNODES * DDIM + 255) / 256, 256>>>(ptmp, 0, g1, b1,
                                                          px1, px1t);

    // FFN
    gemm_kernel<<<dim3(FDIM / GN, MB), 256>>>(px1t, pwt + W1_OFF, lin1_b,
                                              nullptr, nullptr, pff1t,
                                              NNODES, FDIM, DDIM, 1.0f, 1, -1);
    gemm_kernel<<<dim3(1, MB), 256>>>(pff1t, pwt + W2_OFF, lin2_b, px1,
                                      ptmp, nullptr, NNODES, DDIM, FDIM,
                                      1.0f, 0, 256);

    // BN2 apply -> output
    bn_apply_kernel<<<(NNODES * DDIM + 255) / 256, 256>>>(ptmp, 256, g2, b2,
                                                          out, nullptr);
}

// round 13
// speedup vs baseline: 1.0765x; 1.0172x over previous
#include <cuda_runtime.h>
#include <cuda_fp16.h>
#include <cstdint>

#define NNODES 50000
#define DDIM 128
#define NH 8
#define HDIM 16
#define FDIM 512
#define E0 800000
#define ETOT 850000
#define EPS_BN 1e-5f
#define NCHUNK 49   // ceil(50000/1024)

// ---------------- scratch (device globals; no allocation allowed) ----------
__device__ __align__(16) __half g_qh[NNODES * DDIM];
__device__ __align__(16) __half g_kh[NNODES * DDIM];
__device__ __align__(16) __half g_vh[NNODES * DDIM];
__device__ __align__(16) __half g_aggt[NNODES * DDIM];
__device__ __align__(16) float  g_x1[NNODES * DDIM];
__device__ __align__(16) __half g_x1t[NNODES * DDIM];
__device__ __align__(16) float  g_tmp[NNODES * DDIM];
__device__ __align__(16) __half g_ff1t[(size_t)NNODES * FDIM];
__device__ __align__(16) __half g_srct[NNODES * DDIM];
__device__ __align__(16) __half g_wt[196608];
__device__ __align__(16) float  g_stats[512];
__device__ int g_src[ETOT];
__device__ int g_dst[ETOT];
__device__ int g_csr[ETOT];
__device__ int g_deg[NNODES];
__device__ int g_rowptr[NNODES + 1];
__device__ int g_cursor[NNODES];
__device__ int g_csum[64];
__device__ int g_is64;

#define WQ_OFF 0
#define WK_OFF 16384
#define WV_OFF 32768
#define WO_OFF 49152
#define W1_OFF 65536
#define W2_OFF 131072
#define NSRC (NNODES * DDIM)
#define NCONV (NSRC + 196608)

// ---------------- convert + prep (merged): fp16 convert, detect, zero -------
__global__ void convert_kernel(const float* __restrict__ src,
                               const float* __restrict__ wq,
                               const float* __restrict__ wk,
                               const float* __restrict__ wv,
                               const float* __restrict__ wo,
                               const float* __restrict__ w1,
                               const float* __restrict__ w2,
                               const unsigned int* __restrict__ ew) {
    int i = blockIdx.x * blockDim.x + threadIdx.x;
    if (i == 0) {
        int nz = 0;
        for (int j = 1; j < 256; j += 2) nz += (ew[j] != 0u);
        g_is64 = (nz == 0) ? 1 : 0;
    }
    if (i < NNODES) g_deg[i] = 0;
    if (i < 512) g_stats[i] = 0.f;
    int stride = gridDim.x * blockDim.x;
    for (int t = i; t < NCONV; t += stride) {
        if (t < NSRC) {
            g_srct[t] = __float2half_rn(src[t]);
        } else {
            int j = t - NSRC;
            float v;
            if (j < WK_OFF)      v = wq[j - WQ_OFF];
            else if (j < WV_OFF) v = wk[j - WK_OFF];
            else if (j < WO_OFF) v = wv[j - WV_OFF];
            else if (j < W1_OFF) v = wo[j - WO_OFF];
            else if (j < W2_OFF) v = w1[j - W1_OFF];
            else                 v = w2[j - W2_OFF];
            g_wt[j] = __float2half_rn(v);
        }
    }
}

// ---------------- decode edges + degree histogram ---------------------------
__global__ void decode_kernel(const unsigned int* __restrict__ w) {
    int e = blockIdx.x * blockDim.x + threadIdx.x;
    if (e >= ETOT) return;
    int s, d;
    if (e < E0) {
        if (g_is64) {
            s = (int)w[2 * (size_t)e];
            d = (int)w[2 * ((size_t)E0 + e)];
        } else {
            s = (int)w[e];
            d = (int)w[E0 + e];
        }
    } else {
        s = d = e - E0;
    }
    g_src[e] = s;
    g_dst[e] = d;
    atomicAdd(&g_deg[d], 1);
}

// ---------------- CSR build --------------------------------------------------
__global__ void scan1_kernel() {
    __shared__ int sh[1024];
    int t = threadIdx.x;
    int i = blockIdx.x * 1024 + t;
    int v = (i < NNODES) ? g_deg[i] : 0;
    sh[t] = v;
    __syncthreads();
    for (int off = 1; off < 1024; off <<= 1) {
        int x = (t >= off) ? sh[t - off] : 0;
        __syncthreads();
        sh[t] += x;
        __syncthreads();
    }
    if (i < NNODES) g_rowptr[i] = sh[t] - v;
    if (t == 1023) g_csum[blockIdx.x] = sh[1023];
}

// scan3 with folded chunk-prefix (scan2 eliminated). Each 256-thread block
// lies entirely within one 1024-chunk (256 | 1024), so the chunk prefix is
// uniform per block.
__global__ void scan3_kernel() {
    __shared__ int pref;
    if (threadIdx.x == 0) {
        int c = (blockIdx.x * 256) >> 10;
        int run = 0;
        for (int j = 0; j < c; j++) run += g_csum[j];
        pref = run;
    }
    __syncthreads();
    int i = blockIdx.x * blockDim.x + threadIdx.x;
    if (i < NNODES) {
        int rp = g_rowptr[i] + pref;
        g_rowptr[i] = rp;
        g_cursor[i] = rp;
    }
    if (i == 0) g_rowptr[NNODES] = ETOT;
}

__global__ void scatter_kernel() {
    int e = blockIdx.x * blockDim.x + threadIdx.x;
    if (e >= ETOT) return;
    int pos = atomicAdd(&g_cursor[g_dst[e]], 1);
    g_csr[pos] = g_src[e];
}

// ---------------- FP16 tensor-core GEMM (m16n8k16 + ldmatrix) ---------------
// Block 128x128, k-tile 32 halves, warp tile 64x32 (2x4 warps), 256 threads.
#define GM 128
#define GN 128
#define KT 32
#define SK 20
#define BUFB (GM * SK * 4)

__device__ __forceinline__ void mma16(float c[4],
                                      unsigned a0, unsigned a1, unsigned a2, unsigned a3,
                                      unsigned b0, unsigned b1) {
    asm volatile(
        "mma.sync.aligned.m16n8k16.row.col.f32.f16.f16.f32 "
        "{%0,%1,%2,%3}, {%4,%5,%6,%7}, {%8,%9}, {%0,%1,%2,%3};"
        : "+f"(c[0]), "+f"(c[1]), "+f"(c[2]), "+f"(c[3])
        : "r"(a0), "r"(a1), "r"(a2), "r"(a3), "r"(b0), "r"(b1));
}

#define LDSM4(r0, r1, r2, r3, addr) \
    asm volatile("ldmatrix.sync.aligned.m8n8.x4.shared.b16 {%0,%1,%2,%3}, [%4];" \
                 : "=r"(r0), "=r"(r1), "=r"(r2), "=r"(r3) : "r"(addr))

__device__ __forceinline__ float2 lrelu2(float2 o, int act) {
    if (act) {
        o.x = o.x > 0.f ? o.x : 0.01f * o.x;
        o.y = o.y > 0.f ? o.y : 0.01f * o.y;
    }
    return o;
}

__device__ __forceinline__ void gemm_body(
    const __half* __restrict__ A, const __half* __restrict__ B,
    const float* __restrict__ bias, const float* __restrict__ res,
    float* __restrict__ C, __half* __restrict__ Ct,
    int M, int Nn, int K, float alpha, int act, int stats_off,
    int bm, int bn)
{
    __shared__ __align__(16) unsigned As[2][GM][SK];
    __shared__ __align__(16) unsigned Bs[2][GN][SK];
    int tid = threadIdx.x;
    int warp = tid >> 5, lane = tid & 31;
    int wm = warp >> 2, wn = warp & 3;
    int gid = lane >> 2, ctg = lane & 3;
    int lg = lane >> 3, l8 = lane & 7;

    int lrow = tid & 127;
    int kh = (tid >> 7) * 8;
    int kw = K >> 1;
    const unsigned* Ap = (const unsigned*)A + (size_t)(bm + lrow) * kw + kh;
    const unsigned* Bp = (const unsigned*)B + (size_t)(bn + lrow) * kw + kh;
    bool aok = (bm + lrow) < M;

    unsigned sA = (unsigned)__cvta_generic_to_shared(&As[0][0][0]);
    unsigned sB = (unsigned)__cvta_generic_to_shared(&Bs[0][0][0]);
    unsigned aBase = sA + (unsigned)((wm * 64 + (lg & 1) * 8 + l8) * (SK * 4)
                                     + (lg >> 1) * 16);
    unsigned bBase = sB + (unsigned)((wn * 32 + (lg >> 1) * 8 + l8) * (SK * 4)
                                     + (lg & 1) * 16);

    float c[4][4][4];
#pragma unroll
    for (int mt = 0; mt < 4; mt++)
#pragma unroll
        for (int nt = 0; nt < 4; nt++)
#pragma unroll
            for (int r = 0; r < 4; r++) c[mt][nt][r] = 0.f;

    const uint4 z4 = make_uint4(0u, 0u, 0u, 0u);
    uint4 a0v = aok ? *(const uint4*)Ap : z4;
    uint4 a1v = aok ? *(const uint4*)(Ap + 4) : z4;
    uint4 b0v = *(const uint4*)Bp;
    uint4 b1v = *(const uint4*)(Bp + 4);
    *(uint4*)&As[0][lrow][kh]     = a0v;
    *(uint4*)&As[0][lrow][kh + 4] = a1v;
    *(uint4*)&Bs[0][lrow][kh]     = b0v;
    *(uint4*)&Bs[0][lrow][kh + 4] = b1v;
    __syncthreads();

    int nk = K / KT;
    for (int kt = 0; kt < nk; kt++) {
        int cur = kt & 1;
        int nxt = cur ^ 1;
        bool more = (kt + 1) < nk;
        if (more) {
            int off = (kt + 1) * 16;
            a0v = aok ? *(const uint4*)(Ap + off) : z4;
            a1v = aok ? *(const uint4*)(Ap + off + 4) : z4;
            b0v = *(const uint4*)(Bp + off);
            b1v = *(const uint4*)(Bp + off + 4);
        }
        unsigned aB = aBase + cur * BUFB;
        unsigned bB = bBase + cur * BUFB;
#pragma unroll
        for (int ks = 0; ks < 2; ks++) {
            unsigned ksoff = ks * 32;
            unsigned af[4][4], bf[4][2];
#pragma unroll
            for (int mt = 0; mt < 4; mt++)
                LDSM4(af[mt][0], af[mt][1], af[mt][2], af[mt][3],
                      aB + mt * (16 * SK * 4) + ksoff);
#pragma unroll
            for (int np = 0; np < 2; np++)
                LDSM4(bf[np * 2][0], bf[np * 2][1], bf[np * 2 + 1][0],
                      bf[np * 2 + 1][1], bB + np * (16 * SK * 4) + ksoff);
#pragma unroll
            for (int mt = 0; mt < 4; mt++)
#pragma unroll
                for (int nt = 0; nt < 4; nt++)
                    mma16(c[mt][nt], af[mt][0], af[mt][1], af[mt][2], af[mt][3],
                          bf[nt][0], bf[nt][1]);
        }
        if (more) {
            *(uint4*)&As[nxt][lrow][kh]     = a0v;
            *(uint4*)&As[nxt][lrow][kh + 4] = a1v;
            *(uint4*)&Bs[nxt][lrow][kh]     = b0v;
            *(uint4*)&Bs[nxt][lrow][kh + 4] = b1v;
            __syncthreads();
        }
    }

    float ssum[4][2] = {}, ssq[4][2] = {};
#pragma unroll
    for (int nt = 0; nt < 4; nt++) {
        int col = bn + wn * 32 + nt * 8 + 2 * ctg;
        float2 bb = make_float2(0.f, 0.f);
        if (bias) bb = *(const float2*)(bias + col);
#pragma unroll
        for (int mt = 0; mt < 4; mt++) {
            int r0 = bm + wm * 64 + mt * 16 + gid;
            int r1 = r0 + 8;
            if (r0 < M) {
                float2 rv = res ? *(const float2*)(res + (size_t)r0 * Nn + col)
                                : make_float2(0.f, 0.f);
                float2 o;
                o.x = (c[mt][nt][0] + bb.x) * alpha + rv.x;
                o.y = (c[mt][nt][1] + bb.y) * alpha + rv.y;
                o = lrelu2(o, act);
                if (C) *(float2*)(C + (size_t)r0 * Nn + col) = o;
                if (Ct) *(__half2*)(Ct + (size_t)r0 * Nn + col) =
                            __floats2half2_rn(o.x, o.y);
                ssum[nt][0] += o.x; ssum[nt][1] += o.y;
                ssq[nt][0] += o.x * o.x; ssq[nt][1] += o.y * o.y;
            }
            if (r1 < M) {
                float2 rv = res ? *(const float2*)(res + (size_t)r1 * Nn + col)
                                : make_float2(0.f, 0.f);
                float2 o;
                o.x = (c[mt][nt][2] + bb.x) * alpha + rv.x;
                o.y = (c[mt][nt][3] + bb.y) * alpha + rv.y;
                o = lrelu2(o, act);
                if (C) *(float2*)(C + (size_t)r1 * Nn + col) = o;
                if (Ct) *(__half2*)(Ct + (size_t)r1 * Nn + col) =
                            __floats2half2_rn(o.x, o.y);
                ssum[nt][0] += o.x; ssum[nt][1] += o.y;
                ssq[nt][0] += o.x * o.x; ssq[nt][1] += o.y * o.y;
            }
        }
    }

    if (stats_off >= 0) {
        __syncthreads();
        float* sh = (float*)&As[0][0][0];
        sh[tid] = 0.f;
        __syncthreads();
#pragma unroll
        for (int nt = 0; nt < 4; nt++) {
            int cl = wn * 32 + nt * 8 + 2 * ctg;
            atomicAdd(&sh[cl], ssum[nt][0]);
            atomicAdd(&sh[cl + 1], ssum[nt][1]);
            atomicAdd(&sh[128 + cl], ssq[nt][0]);
            atomicAdd(&sh[128 + cl + 1], ssq[nt][1]);
        }
        __syncthreads();
        atomicAdd(&g_stats[stats_off + tid], sh[tid]);
    }
}

__global__ __launch_bounds__(256, 2) void gemm_kernel(
    const __half* __restrict__ A, const __half* __restrict__ B,
    const float* __restrict__ bias, const float* __restrict__ res,
    float* __restrict__ C, __half* __restrict__ Ct,
    int M, int Nn, int K, float alpha, int act, int stats_off)
{
    gemm_body(A, B, bias, res, C, Ct, M, Nn, K, alpha, act, stats_off,
              blockIdx.y * GM, blockIdx.x * GN);
}

__global__ __launch_bounds__(256, 2) void qkv_gemm_kernel(const float* __restrict__ qb) {
    int z = blockIdx.z;
    const __half* B = g_wt + ((z == 0) ? WQ_OFF : (z == 1) ? WK_OFF : WV_OFF);
    __half* Ct = (z == 0) ? g_qh : (z == 1) ? g_kh : g_vh;
    const float* bias = (z == 0) ? qb : nullptr;
    float alpha = (z == 0) ? 0.25f : 1.0f;
    gemm_body(g_srct, B, bias, nullptr, nullptr, Ct,
              NNODES, DDIM, DDIM, alpha, 0, -1, blockIdx.y * GM, 0);
}

// ---------------- warp-per-node CSR attention aggregation -------------------
// fp16 gathers; kr AND vr batched up-front (one L2 round-trip per 4-edge
// group); deduped exp.
__global__ void node_agg_kernel() {
    int node = (blockIdx.x * blockDim.x + threadIdx.x) >> 5;
    if (node >= NNODES) return;
    int lane = threadIdx.x & 31;
    uint2 qa = *((const uint2*)(g_qh + (size_t)node * DDIM) + lane);
    float2 qf0 = __half22float2(*(__half2*)&qa.x);
    float2 qf1 = __half22float2(*(__half2*)&qa.y);
    float4 acc = make_float4(0.f, 0.f, 0.f, 0.f);
    float den = 0.f;
    int beg = g_rowptr[node], end = g_rowptr[node + 1];
    int i = beg;
    int esel = lane & 3;
    int gbase = lane & ~3;
    for (; i + 4 <= end; i += 4) {
        int sv = (lane < 4) ? g_csr[i + lane] : 0;
        int s[4];
#pragma unroll
        for (int j = 0; j < 4; j++) s[j] = __shfl_sync(0xffffffffu, sv, j);
        // batch all 8 gathers before any dependent math
        uint2 kr[4], vr[4];
#pragma unroll
        for (int j = 0; j < 4; j++)
            kr[j] = *((const uint2*)(g_kh + (size_t)s[j] * DDIM) + lane);
#pragma unroll
        for (int j = 0; j < 4; j++)
            vr[j] = *((const uint2*)(g_vh + (size_t)s[j] * DDIM) + lane);
        float p[4];
#pragma unroll
        for (int j = 0; j < 4; j++) {
            float2 k0 = __half22float2(*(__half2*)&kr[j].x);
            float2 k1 = __half22float2(*(__half2*)&kr[j].y);
            p[j] = k0.x * qf0.x + k0.y * qf0.y + k1.x * qf1.x + k1.y * qf1.y;
            p[j] += __shfl_xor_sync(0xffffffffu, p[j], 1);
            p[j] += __shfl_xor_sync(0xffffffffu, p[j], 2);
        }
        float eo = __expf(esel == 0 ? p[0] : esel == 1 ? p[1]
                          : esel == 2 ? p[2] : p[3]);
        float e[4];
#pragma unroll
        for (int j = 0; j < 4; j++)
            e[j] = __shfl_sync(0xffffffffu, eo, gbase + j);
#pragma unroll
        for (int j = 0; j < 4; j++) {
            den += e[j];
            float2 v0 = __half22float2(*(__half2*)&vr[j].x);
            float2 v1 = __half22float2(*(__half2*)&vr[j].y);
            acc.x += e[j] * v0.x; acc.y += e[j] * v0.y;
            acc.z += e[j] * v1.x; acc.w += e[j] * v1.y;
        }
    }
    for (; i < end; i++) {
        int s0 = __shfl_sync(0xffffffffu, (lane == 0) ? g_csr[i] : 0, 0);
        uint2 kr = *((const uint2*)(g_kh + (size_t)s0 * DDIM) + lane);
        uint2 vr = *((const uint2*)(g_vh + (size_t)s0 * DDIM) + lane);
        float2 k0 = __half22float2(*(__half2*)&kr.x);
        float2 k1 = __half22float2(*(__half2*)&kr.y);
        float p = k0.x * qf0.x + k0.y * qf0.y + k1.x * qf1.x + k1.y * qf1.y;
        p += __shfl_xor_sync(0xffffffffu, p, 1);
        p += __shfl_xor_sync(0xffffffffu, p, 2);
        float e0 = __expf(p);
        den += e0;
        float2 v0 = __half22float2(*(__half2*)&vr.x);
        float2 v1 = __half22float2(*(__half2*)&vr.y);
        acc.x += e0 * v0.x; acc.y += e0 * v0.y;
        acc.z += e0 * v1.x; acc.w += e0 * v1.y;
    }
    float inv = 1.f / (den + 1e-16f);
    __half2 o0 = __floats2half2_rn(acc.x * inv, acc.y * inv);
    __half2 o1 = __floats2half2_rn(acc.z * inv, acc.w * inv);
    uint2 o;
    o.x = *(unsigned*)&o0;
    o.y = *(unsigned*)&o1;
    *((uint2*)(g_aggt + (size_t)node * DDIM) + lane) = o;
}

// ---------------- BatchNorm apply -------------------------------------------
__global__ void bn_apply_kernel(const float* __restrict__ X, int off,
                                const float* __restrict__ gamma,
                                const float* __restrict__ beta,
                                float* __restrict__ Y,
                                __half* __restrict__ Yt) {
    int i = blockIdx.x * blockDim.x + threadIdx.x;
    if (i >= NNODES * DDIM) return;
    int j = i & (DDIM - 1);
    const float invn = 1.0f / NNODES;
    float mean = g_stats[off + j] * invn;
    float var = g_stats[off + DDIM + j] * invn - mean * mean;
    float val = (X[i] - mean) * rsqrtf(var + EPS_BN) * gamma[j] + beta[j];
    Y[i] = val;
    if (Yt) Yt[i] = __float2half_rn(val);
}

// ---------------- launch ------------------------------------------------------
extern "C" void kernel_launch(void* const* d_in, const int* in_sizes, int n_in,
                              void* d_out, int out_size) {
    const float* src    = (const float*)d_in[0];
    const unsigned int* ei = (const unsigned int*)d_in[1];
    const float* q_w    = (const float*)d_in[2];
    const float* q_b    = (const float*)d_in[3];
    const float* k_w    = (const float*)d_in[4];
    const float* v_w    = (const float*)d_in[5];
    const float* out_w  = (const float*)d_in[6];
    const float* out_b  = (const float*)d_in[7];
    const float* g1     = (const float*)d_in[8];
    const float* b1     = (const float*)d_in[9];
    const float* lin1_w = (const float*)d_in[10];
    const float* lin1_b = (const float*)d_in[11];
    const float* lin2_w = (const float*)d_in[12];
    const float* lin2_b = (const float*)d_in[13];
    const float* g2     = (const float*)d_in[14];
    const float* b2     = (const float*)d_in[15];
    float* out = (float*)d_out;

    __half *paggt, *px1t, *pff1t, *pwt;
    float *px1, *ptmp;
    cudaGetSymbolAddress((void**)&paggt, g_aggt);
    cudaGetSymbolAddress((void**)&px1,   g_x1);
    cudaGetSymbolAddress((void**)&px1t,  g_x1t);
    cudaGetSymbolAddress((void**)&ptmp,  g_tmp);
    cudaGetSymbolAddress((void**)&pff1t, g_ff1t);
    cudaGetSymbolAddress((void**)&pwt,   g_wt);

    const int MB = (NNODES + GM - 1) / GM;  // 391

    convert_kernel<<<512, 256>>>(src, q_w, k_w, v_w, out_w, lin1_w, lin2_w, ei);
    decode_kernel<<<(ETOT + 255) / 256, 256>>>(ei);
    scan1_kernel<<<NCHUNK, 1024>>>();
    qkv_gemm_kernel<<<dim3(1, MB, 3), 256>>>(q_b);
    scan3_kernel<<<(NNODES + 255) / 256, 256>>>();
    scatter_kernel<<<(ETOT + 255) / 256, 256>>>();

    // attention aggregation (CSR, warp per node)
    node_agg_kernel<<<(NNODES * 32 + 255) / 256, 256>>>();

    // out projection + residual + fused BN1 stats
    gemm_kernel<<<dim3(1, MB), 256>>>(paggt, pwt + WO_OFF, out_b, src,
                                      ptmp, nullptr, NNODES, DDIM, DDIM,
                                      1.0f, 0, 0);

    // BN1 apply (fp32 + fp16)
    bn_apply_kernel<<<(NNODES * DDIM + 255) / 256, 256>>>(ptmp, 0, g1, b1,
                                                          px1, px1t);

    // FFN
    gemm_kernel<<<dim3(FDIM / GN, MB), 256>>>(px1t, pwt + W1_OFF, lin1_b,
                                              nullptr, nullptr, pff1t,
                                              NNODES, FDIM, DDIM, 1.0f, 1, -1);
    gemm_kernel<<<dim3(1, MB), 256>>>(pff1t, pwt + W2_OFF, lin2_b, px1,
                                      ptmp, nullptr, NNODES, DDIM, FDIM,
                                      1.0f, 0, 256);

    // BN2 apply -> output
    bn_apply_kernel<<<(NNODES * DDIM + 255) / 256, 256>>>(ptmp, 256, g2, b2,
                                                          out, nullptr);
}

// round 14
// speedup vs baseline: 1.1032x; 1.0248x over previous
#include <cuda_runtime.h>
#include <cuda_fp16.h>
#include <cstdint>

#define NNODES 50000
#define DDIM 128
#define NH 8
#define HDIM 16
#define FDIM 512
#define E0 800000
#define ETOT 850000
#define EPS_BN 1e-5f
#define NCHUNK 49   // ceil(50000/1024)

// ---------------- scratch (device globals; no allocation allowed) ----------
__device__ __align__(16) __half g_qh[NNODES * DDIM];
__device__ __align__(16) __half g_kh[NNODES * DDIM];
__device__ __align__(16) __half g_vh[NNODES * DDIM];
__device__ __align__(16) __half g_aggt[NNODES * DDIM];
__device__ __align__(16) float  g_x1[NNODES * DDIM];
__device__ __align__(16) __half g_x1t[NNODES * DDIM];
__device__ __align__(16) float  g_tmp[NNODES * DDIM];
__device__ __align__(16) __half g_ff1t[(size_t)NNODES * FDIM];
__device__ __align__(16) __half g_srct[NNODES * DDIM];
__device__ __align__(16) __half g_wt[196608];
__device__ __align__(16) float  g_stats[512];
__device__ int g_src[ETOT];
__device__ int g_dst[ETOT];
__device__ int g_csr[ETOT];
__device__ int g_deg[NNODES];
__device__ int g_rowptr[NNODES + 1];
__device__ int g_cursor[NNODES];
__device__ int g_csum[64];
__device__ int g_is64;

#define WQ_OFF 0
#define WK_OFF 16384
#define WV_OFF 32768
#define WO_OFF 49152
#define W1_OFF 65536
#define W2_OFF 131072
#define NSRC (NNODES * DDIM)
#define NCONV (NSRC + 196608)

// ---------------- convert + prep (merged): fp16 convert, detect, zero -------
__global__ void convert_kernel(const float* __restrict__ src,
                               const float* __restrict__ wq,
                               const float* __restrict__ wk,
                               const float* __restrict__ wv,
                               const float* __restrict__ wo,
                               const float* __restrict__ w1,
                               const float* __restrict__ w2,
                               const unsigned int* __restrict__ ew) {
    int i = blockIdx.x * blockDim.x + threadIdx.x;
    if (i == 0) {
        int nz = 0;
        for (int j = 1; j < 256; j += 2) nz += (ew[j] != 0u);
        g_is64 = (nz == 0) ? 1 : 0;
    }
    if (i < NNODES) g_deg[i] = 0;
    if (i < 512) g_stats[i] = 0.f;
    int stride = gridDim.x * blockDim.x;
    for (int t = i; t < NCONV; t += stride) {
        if (t < NSRC) {
            g_srct[t] = __float2half_rn(src[t]);
        } else {
            int j = t - NSRC;
            float v;
            if (j < WK_OFF)      v = wq[j - WQ_OFF];
            else if (j < WV_OFF) v = wk[j - WK_OFF];
            else if (j < WO_OFF) v = wv[j - WV_OFF];
            else if (j < W1_OFF) v = wo[j - WO_OFF];
            else if (j < W2_OFF) v = w1[j - W1_OFF];
            else                 v = w2[j - W2_OFF];
            g_wt[j] = __float2half_rn(v);
        }
    }
}

// ---------------- decode edges + degree histogram ---------------------------
__global__ void decode_kernel(const unsigned int* __restrict__ w) {
    int e = blockIdx.x * blockDim.x + threadIdx.x;
    if (e >= ETOT) return;
    int s, d;
    if (e < E0) {
        if (g_is64) {
            s = (int)w[2 * (size_t)e];
            d = (int)w[2 * ((size_t)E0 + e)];
        } else {
            s = (int)w[e];
            d = (int)w[E0 + e];
        }
    } else {
        s = d = e - E0;
    }
    g_src[e] = s;
    g_dst[e] = d;
    atomicAdd(&g_deg[d], 1);
}

// ---------------- CSR build --------------------------------------------------
__global__ void scan1_kernel() {
    __shared__ int sh[1024];
    int t = threadIdx.x;
    int i = blockIdx.x * 1024 + t;
    int v = (i < NNODES) ? g_deg[i] : 0;
    sh[t] = v;
    __syncthreads();
    for (int off = 1; off < 1024; off <<= 1) {
        int x = (t >= off) ? sh[t - off] : 0;
        __syncthreads();
        sh[t] += x;
        __syncthreads();
    }
    if (i < NNODES) g_rowptr[i] = sh[t] - v;
    if (t == 1023) g_csum[blockIdx.x] = sh[1023];
}

__global__ void scan3_kernel() {
    __shared__ int pref;
    if (threadIdx.x == 0) {
        int c = (blockIdx.x * 256) >> 10;
        int run = 0;
        for (int j = 0; j < c; j++) run += g_csum[j];
        pref = run;
    }
    __syncthreads();
    int i = blockIdx.x * blockDim.x + threadIdx.x;
    if (i < NNODES) {
        int rp = g_rowptr[i] + pref;
        g_rowptr[i] = rp;
        g_cursor[i] = rp;
    }
    if (i == 0) g_rowptr[NNODES] = ETOT;
}

__global__ void scatter_kernel() {
    int e = blockIdx.x * blockDim.x + threadIdx.x;
    if (e >= ETOT) return;
    int pos = atomicAdd(&g_cursor[g_dst[e]], 1);
    g_csr[pos] = g_src[e];
}

// ---------------- FP16 tensor-core GEMM (m16n8k16 + ldmatrix) ---------------
#define GM 128
#define GN 128
#define KT 32
#define SK 20
#define BUFB (GM * SK * 4)

__device__ __forceinline__ void mma16(float c[4],
                                      unsigned a0, unsigned a1, unsigned a2, unsigned a3,
                                      unsigned b0, unsigned b1) {
    asm volatile(
        "mma.sync.aligned.m16n8k16.row.col.f32.f16.f16.f32 "
        "{%0,%1,%2,%3}, {%4,%5,%6,%7}, {%8,%9}, {%0,%1,%2,%3};"
        : "+f"(c[0]), "+f"(c[1]), "+f"(c[2]), "+f"(c[3])
        : "r"(a0), "r"(a1), "r"(a2), "r"(a3), "r"(b0), "r"(b1));
}

#define LDSM4(r0, r1, r2, r3, addr) \
    asm volatile("ldmatrix.sync.aligned.m8n8.x4.shared.b16 {%0,%1,%2,%3}, [%4];" \
                 : "=r"(r0), "=r"(r1), "=r"(r2), "=r"(r3) : "r"(addr))

__device__ __forceinline__ float2 lrelu2(float2 o, int act) {
    if (act) {
        o.x = o.x > 0.f ? o.x : 0.01f * o.x;
        o.y = o.y > 0.f ? o.y : 0.01f * o.y;
    }
    return o;
}

__device__ __forceinline__ void gemm_body(
    const __half* __restrict__ A, const __half* __restrict__ B,
    const float* __restrict__ bias, const float* __restrict__ res,
    float* __restrict__ C, __half* __restrict__ Ct,
    int M, int Nn, int K, float alpha, int act, int stats_off,
    int bm, int bn)
{
    __shared__ __align__(16) unsigned As[2][GM][SK];
    __shared__ __align__(16) unsigned Bs[2][GN][SK];
    int tid = threadIdx.x;
    int warp = tid >> 5, lane = tid & 31;
    int wm = warp >> 2, wn = warp & 3;
    int gid = lane >> 2, ctg = lane & 3;
    int lg = lane >> 3, l8 = lane & 7;

    int lrow = tid & 127;
    int kh = (tid >> 7) * 8;
    int kw = K >> 1;
    const unsigned* Ap = (const unsigned*)A + (size_t)(bm + lrow) * kw + kh;
    const unsigned* Bp = (const unsigned*)B + (size_t)(bn + lrow) * kw + kh;
    bool aok = (bm + lrow) < M;

    unsigned sA = (unsigned)__cvta_generic_to_shared(&As[0][0][0]);
    unsigned sB = (unsigned)__cvta_generic_to_shared(&Bs[0][0][0]);
    unsigned aBase = sA + (unsigned)((wm * 64 + (lg & 1) * 8 + l8) * (SK * 4)
                                     + (lg >> 1) * 16);
    unsigned bBase = sB + (unsigned)((wn * 32 + (lg >> 1) * 8 + l8) * (SK * 4)
                                     + (lg & 1) * 16);

    float c[4][4][4];
#pragma unroll
    for (int mt = 0; mt < 4; mt++)
#pragma unroll
        for (int nt = 0; nt < 4; nt++)
#pragma unroll
            for (int r = 0; r < 4; r++) c[mt][nt][r] = 0.f;

    const uint4 z4 = make_uint4(0u, 0u, 0u, 0u);
    uint4 a0v = aok ? *(const uint4*)Ap : z4;
    uint4 a1v = aok ? *(const uint4*)(Ap + 4) : z4;
    uint4 b0v = *(const uint4*)Bp;
    uint4 b1v = *(const uint4*)(Bp + 4);
    *(uint4*)&As[0][lrow][kh]     = a0v;
    *(uint4*)&As[0][lrow][kh + 4] = a1v;
    *(uint4*)&Bs[0][lrow][kh]     = b0v;
    *(uint4*)&Bs[0][lrow][kh + 4] = b1v;
    __syncthreads();

    int nk = K / KT;
    for (int kt = 0; kt < nk; kt++) {
        int cur = kt & 1;
        int nxt = cur ^ 1;
        bool more = (kt + 1) < nk;
        if (more) {
            int off = (kt + 1) * 16;
            a0v = aok ? *(const uint4*)(Ap + off) : z4;
            a1v = aok ? *(const uint4*)(Ap + off + 4) : z4;
            b0v = *(const uint4*)(Bp + off);
            b1v = *(const uint4*)(Bp + off + 4);
        }
        unsigned aB = aBase + cur * BUFB;
        unsigned bB = bBase + cur * BUFB;
#pragma unroll
        for (int ks = 0; ks < 2; ks++) {
            unsigned ksoff = ks * 32;
            unsigned af[4][4], bf[4][2];
#pragma unroll
            for (int mt = 0; mt < 4; mt++)
                LDSM4(af[mt][0], af[mt][1], af[mt][2], af[mt][3],
                      aB + mt * (16 * SK * 4) + ksoff);
#pragma unroll
            for (int np = 0; np < 2; np++)
                LDSM4(bf[np * 2][0], bf[np * 2][1], bf[np * 2 + 1][0],
                      bf[np * 2 + 1][1], bB + np * (16 * SK * 4) + ksoff);
#pragma unroll
            for (int mt = 0; mt < 4; mt++)
#pragma unroll
                for (int nt = 0; nt < 4; nt++)
                    mma16(c[mt][nt], af[mt][0], af[mt][1], af[mt][2], af[mt][3],
                          bf[nt][0], bf[nt][1]);
        }
        if (more) {
            *(uint4*)&As[nxt][lrow][kh]     = a0v;
            *(uint4*)&As[nxt][lrow][kh + 4] = a1v;
            *(uint4*)&Bs[nxt][lrow][kh]     = b0v;
            *(uint4*)&Bs[nxt][lrow][kh + 4] = b1v;
            __syncthreads();
        }
    }

    float ssum[4][2] = {}, ssq[4][2] = {};
#pragma unroll
    for (int nt = 0; nt < 4; nt++) {
        int col = bn + wn * 32 + nt * 8 + 2 * ctg;
        float2 bb = make_float2(0.f, 0.f);
        if (bias) bb = *(const float2*)(bias + col);
#pragma unroll
        for (int mt = 0; mt < 4; mt++) {
            int r0 = bm + wm * 64 + mt * 16 + gid;
            int r1 = r0 + 8;
            if (r0 < M) {
                float2 rv = res ? *(const float2*)(res + (size_t)r0 * Nn + col)
                                : make_float2(0.f, 0.f);
                float2 o;
                o.x = (c[mt][nt][0] + bb.x) * alpha + rv.x;
                o.y = (c[mt][nt][1] + bb.y) * alpha + rv.y;
                o = lrelu2(o, act);
                if (C) *(float2*)(C + (size_t)r0 * Nn + col) = o;
                if (Ct) *(__half2*)(Ct + (size_t)r0 * Nn + col) =
                            __floats2half2_rn(o.x, o.y);
                ssum[nt][0] += o.x; ssum[nt][1] += o.y;
                ssq[nt][0] += o.x * o.x; ssq[nt][1] += o.y * o.y;
            }
            if (r1 < M) {
                float2 rv = res ? *(const float2*)(res + (size_t)r1 * Nn + col)
                                : make_float2(0.f, 0.f);
                float2 o;
                o.x = (c[mt][nt][2] + bb.x) * alpha + rv.x;
                o.y = (c[mt][nt][3] + bb.y) * alpha + rv.y;
                o = lrelu2(o, act);
                if (C) *(float2*)(C + (size_t)r1 * Nn + col) = o;
                if (Ct) *(__half2*)(Ct + (size_t)r1 * Nn + col) =
                            __floats2half2_rn(o.x, o.y);
                ssum[nt][0] += o.x; ssum[nt][1] += o.y;
                ssq[nt][0] += o.x * o.x; ssq[nt][1] += o.y * o.y;
            }
        }
    }

    if (stats_off >= 0) {
        __syncthreads();
        float* sh = (float*)&As[0][0][0];
        sh[tid] = 0.f;
        __syncthreads();
#pragma unroll
        for (int nt = 0; nt < 4; nt++) {
            int cl = wn * 32 + nt * 8 + 2 * ctg;
            atomicAdd(&sh[cl], ssum[nt][0]);
            atomicAdd(&sh[cl + 1], ssum[nt][1]);
            atomicAdd(&sh[128 + cl], ssq[nt][0]);
            atomicAdd(&sh[128 + cl + 1], ssq[nt][1]);
        }
        __syncthreads();
        atomicAdd(&g_stats[stats_off + tid], sh[tid]);
    }
}

__global__ __launch_bounds__(256, 2) void gemm_kernel(
    const __half* __restrict__ A, const __half* __restrict__ B,
    const float* __restrict__ bias, const float* __restrict__ res,
    float* __restrict__ C, __half* __restrict__ Ct,
    int M, int Nn, int K, float alpha, int act, int stats_off)
{
    gemm_body(A, B, bias, res, C, Ct, M, Nn, K, alpha, act, stats_off,
              blockIdx.y * GM, blockIdx.x * GN);
}

__global__ __launch_bounds__(256, 2) void qkv_gemm_kernel(const float* __restrict__ qb) {
    int z = blockIdx.z;
    const __half* B = g_wt + ((z == 0) ? WQ_OFF : (z == 1) ? WK_OFF : WV_OFF);
    __half* Ct = (z == 0) ? g_qh : (z == 1) ? g_kh : g_vh;
    const float* bias = (z == 0) ? qb : nullptr;
    float alpha = (z == 0) ? 0.25f : 1.0f;
    gemm_body(g_srct, B, bias, nullptr, nullptr, Ct,
              NNODES, DDIM, DDIM, alpha, 0, -1, blockIdx.y * GM, 0);
}

// ---------------- warp-per-node CSR attention aggregation -------------------
__global__ void node_agg_kernel() {
    int node = (blockIdx.x * blockDim.x + threadIdx.x) >> 5;
    if (node >= NNODES) return;
    int lane = threadIdx.x & 31;
    uint2 qa = *((const uint2*)(g_qh + (size_t)node * DDIM) + lane);
    float2 qf0 = __half22float2(*(__half2*)&qa.x);
    float2 qf1 = __half22float2(*(__half2*)&qa.y);
    float4 acc = make_float4(0.f, 0.f, 0.f, 0.f);
    float den = 0.f;
    int beg = g_rowptr[node], end = g_rowptr[node + 1];
    int i = beg;
    int esel = lane & 3;
    int gbase = lane & ~3;
    for (; i + 4 <= end; i += 4) {
        int sv = (lane < 4) ? g_csr[i + lane] : 0;
        int s[4];
#pragma unroll
        for (int j = 0; j < 4; j++) s[j] = __shfl_sync(0xffffffffu, sv, j);
        uint2 kr[4], vr[4];
#pragma unroll
        for (int j = 0; j < 4; j++)
            kr[j] = *((const uint2*)(g_kh + (size_t)s[j] * DDIM) + lane);
#pragma unroll
        for (int j = 0; j < 4; j++)
            vr[j] = *((const uint2*)(g_vh + (size_t)s[j] * DDIM) + lane);
        float p[4];
#pragma unroll
        for (int j = 0; j < 4; j++) {
            float2 k0 = __half22float2(*(__half2*)&kr[j].x);
            float2 k1 = __half22float2(*(__half2*)&kr[j].y);
            p[j] = k0.x * qf0.x + k0.y * qf0.y + k1.x * qf1.x + k1.y * qf1.y;
            p[j] += __shfl_xor_sync(0xffffffffu, p[j], 1);
            p[j] += __shfl_xor_sync(0xffffffffu, p[j], 2);
        }
        float eo = __expf(esel == 0 ? p[0] : esel == 1 ? p[1]
                          : esel == 2 ? p[2] : p[3]);
        float e[4];
#pragma unroll
        for (int j = 0; j < 4; j++)
            e[j] = __shfl_sync(0xffffffffu, eo, gbase + j);
#pragma unroll
        for (int j = 0; j < 4; j++) {
            den += e[j];
            float2 v0 = __half22float2(*(__half2*)&vr[j].x);
            float2 v1 = __half22float2(*(__half2*)&vr[j].y);
            acc.x += e[j] * v0.x; acc.y += e[j] * v0.y;
            acc.z += e[j] * v1.x; acc.w += e[j] * v1.y;
        }
    }
    for (; i < end; i++) {
        int s0 = __shfl_sync(0xffffffffu, (lane == 0) ? g_csr[i] : 0, 0);
        uint2 kr = *((const uint2*)(g_kh + (size_t)s0 * DDIM) + lane);
        uint2 vr = *((const uint2*)(g_vh + (size_t)s0 * DDIM) + lane);
        float2 k0 = __half22float2(*(__half2*)&kr.x);
        float2 k1 = __half22float2(*(__half2*)&kr.y);
        float p = k0.x * qf0.x + k0.y * qf0.y + k1.x * qf1.x + k1.y * qf1.y;
        p += __shfl_xor_sync(0xffffffffu, p, 1);
        p += __shfl_xor_sync(0xffffffffu, p, 2);
        float e0 = __expf(p);
        den += e0;
        float2 v0 = __half22float2(*(__half2*)&vr.x);
        float2 v1 = __half22float2(*(__half2*)&vr.y);
        acc.x += e0 * v0.x; acc.y += e0 * v0.y;
        acc.z += e0 * v1.x; acc.w += e0 * v1.y;
    }
    float inv = 1.f / (den + 1e-16f);
    __half2 o0 = __floats2half2_rn(acc.x * inv, acc.y * inv);
    __half2 o1 = __floats2half2_rn(acc.z * inv, acc.w * inv);
    uint2 o;
    o.x = *(unsigned*)&o0;
    o.y = *(unsigned*)&o1;
    *((uint2*)(g_aggt + (size_t)node * DDIM) + lane) = o;
}

// ---------------- BatchNorm apply -------------------------------------------
__global__ void bn_apply_kernel(const float* __restrict__ X, int off,
                                const float* __restrict__ gamma,
                                const float* __restrict__ beta,
                                float* __restrict__ Y,
                                __half* __restrict__ Yt) {
    int i = blockIdx.x * blockDim.x + threadIdx.x;
    if (i >= NNODES * DDIM) return;
    int j = i & (DDIM - 1);
    const float invn = 1.0f / NNODES;
    float mean = g_stats[off + j] * invn;
    float var = g_stats[off + DDIM + j] * invn - mean * mean;
    float val = (X[i] - mean) * rsqrtf(var + EPS_BN) * gamma[j] + beta[j];
    Y[i] = val;
    if (Yt) Yt[i] = __float2half_rn(val);
}

// ---------------- launch ------------------------------------------------------
extern "C" void kernel_launch(void* const* d_in, const int* in_sizes, int n_in,
                              void* d_out, int out_size) {
    const float* src    = (const float*)d_in[0];
    const unsigned int* ei = (const unsigned int*)d_in[1];
    const float* q_w    = (const float*)d_in[2];
    const float* q_b    = (const float*)d_in[3];
    const float* k_w    = (const float*)d_in[4];
    const float* v_w    = (const float*)d_in[5];
    const float* out_w  = (const float*)d_in[6];
    const float* out_b  = (const float*)d_in[7];
    const float* g1     = (const float*)d_in[8];
    const float* b1     = (const float*)d_in[9];
    const float* lin1_w = (const float*)d_in[10];
    const float* lin1_b = (const float*)d_in[11];
    const float* lin2_w = (const float*)d_in[12];
    const float* lin2_b = (const float*)d_in[13];
    const float* g2     = (const float*)d_in[14];
    const float* b2     = (const float*)d_in[15];
    float* out = (float*)d_out;

    __half *paggt, *px1t, *pff1t, *pwt;
    float *px1, *ptmp;
    cudaGetSymbolAddress((void**)&paggt, g_aggt);
    cudaGetSymbolAddress((void**)&px1,   g_x1);
    cudaGetSymbolAddress((void**)&px1t,  g_x1t);
    cudaGetSymbolAddress((void**)&ptmp,  g_tmp);
    cudaGetSymbolAddress((void**)&pff1t, g_ff1t);
    cudaGetSymbolAddress((void**)&pwt,   g_wt);

    // one-time side-stream + events (host resources, no device allocation)
    static cudaStream_t s1 = nullptr;
    static cudaEvent_t e0 = nullptr, e1 = nullptr;
    if (s1 == nullptr) {
        cudaStreamCreateWithFlags(&s1, cudaStreamNonBlocking);
        cudaEventCreateWithFlags(&e0, cudaEventDisableTiming);
        cudaEventCreateWithFlags(&e1, cudaEventDisableTiming);
    }

    const int MB = (NNODES + GM - 1) / GM;  // 391

    // main stream: convert (produces srct/wt + is64 + zeroed deg/stats)
    convert_kernel<<<512, 256>>>(src, q_w, k_w, v_w, out_w, lin1_w, lin2_w, ei);
    cudaEventRecord(e0, 0);

    // side stream: CSR build chain, concurrent with qkv GEMM
    cudaStreamWaitEvent(s1, e0, 0);
    decode_kernel<<<(ETOT + 255) / 256, 256, 0, s1>>>(ei);
    scan1_kernel<<<NCHUNK, 1024, 0, s1>>>();
    scan3_kernel<<<(NNODES + 255) / 256, 256, 0, s1>>>();
    scatter_kernel<<<(ETOT + 255) / 256, 256, 0, s1>>>();
    cudaEventRecord(e1, s1);

    // main stream: qkv GEMM overlaps the CSR chain
    qkv_gemm_kernel<<<dim3(1, MB, 3), 256>>>(q_b);
    cudaStreamWaitEvent(0, e1, 0);

    // attention aggregation (CSR, warp per node)
    node_agg_kernel<<<(NNODES * 32 + 255) / 256, 256>>>();

    // out projection + residual + fused BN1 stats
    gemm_kernel<<<dim3(1, MB), 256>>>(paggt, pwt + WO_OFF, out_b, src,
                                      ptmp, nullptr, NNODES, DDIM, DDIM,
                                      1.0f, 0, 0);

    // BN1 apply (fp32 + fp16)
    bn_apply_kernel<<<(NNODES * DDIM + 255) / 256, 256>>>(ptmp, 0, g1, b1,
                                                          px1, px1t);

    // FFN
    gemm_kernel<<<dim3(FDIM / GN, MB), 256>>>(px1t, pwt + W1_OFF, lin1_b,
                                              nullptr, nullptr, pff1t,
                                              NNODES, FDIM, DDIM, 1.0f, 1, -1);
    gemm_kernel<<<dim3(1, MB), 256>>>(pff1t, pwt + W2_OFF, lin2_b, px1,
                                      ptmp, nullptr, NNODES, DDIM, FDIM,
                                      1.0f, 0, 256);

    // BN2 apply -> output
    bn_apply_kernel<<<(NNODES * DDIM + 255) / 256, 256>>>(ptmp, 256, g2, b2,
                                                          out, nullptr);
}